// round 4
// baseline (speedup 1.0000x reference)
#include <cuda_runtime.h>

#define NG 2048
#define NU 16
#define NB 50
#define ND 64
#define FACTOR 0.5f

__global__ __launch_bounds__(256, 6)
void group_embedding_kernel(
    const int*   __restrict__ group_users,   // [G,U]
    const int*   __restrict__ user_lens,     // [G]
    const int*   __restrict__ beh_ids,       // [G,U,B]
    const float* __restrict__ beh_counts,    // [G,U,B]
    const int*   __restrict__ target_user,   // [G]
    const float* __restrict__ user_table,    // [N_USERS, D]
    const float* __restrict__ item_table,    // [N_ITEMS, D]
    const float* __restrict__ sim_vec,       // [N_USERS, D]
    const float* __restrict__ Wq, const float* __restrict__ bq,
    const float* __restrict__ Wk, const float* __restrict__ bk,
    const float* __restrict__ Wv, const float* __restrict__ bv,
    float*       __restrict__ out)           // [G, D]
{
    __shared__ float sSim[NU][ND];     // member similarity vectors (valid rows only)
    __shared__ float sTsim[ND];        // target similarity vector
    __shared__ float sQ[ND];
    __shared__ float sR[ND];           // r = Wk^T Q
    __shared__ float sLogit[NU];
    __shared__ float sWt[NU];
    __shared__ int   sGid[NU];
    __shared__ int   sIds[NU * NB];    // compacted ids
    __shared__ float sCoef[NU * NB];   // compacted w*count
    __shared__ float sPool[16][ND];
    __shared__ float sPooled[ND];
    __shared__ float sQbkSum;
    __shared__ int   sCnt;

    const int g    = blockIdx.x;
    const int tid  = threadIdx.x;
    const int team = tid >> 4;      // 0..15
    const int lane = tid & 15;      // 0..15
    const int l32  = tid & 31;

    int L = user_lens[g];
    if (L < 1)  L = 1;
    if (L > NU) L = NU;

    if (tid == 0) sCnt = 0;

    // ---- Stage L member sim vectors + target sim vector ----
    for (int i = tid; i < (L + 1) * ND; i += 256) {
        int r = i >> 6, d = i & 63;
        int idx = (r < L) ? group_users[g * NU + r] : target_user[g];
        float v = __ldg(sim_vec + (size_t)idx * ND + d);
        if (r < L) sSim[r][d] = v;
        else       sTsim[d]   = v;
    }
    if (tid < NU) sGid[tid] = group_users[g * NU + tid];
    __syncthreads();

    // ---- Q = Wq @ Tsim + bq : 4 threads per row, coalesced 2KB/warp ----
    {
        int d = tid >> 2, q = tid & 3;
        float p = 0.f;
        const float* w = Wq + d * ND + q * 16;
        const float* s = sTsim + q * 16;
        #pragma unroll
        for (int e = 0; e < 16; e++) p += __ldg(w + e) * s[e];
        p += __shfl_xor_sync(0xffffffffu, p, 1);
        p += __shfl_xor_sync(0xffffffffu, p, 2);
        if (q == 0) sQ[d] = p + __ldg(bq + d);
    }
    __syncthreads();

    // ---- r = Wk^T Q (coalesced column access); warp 0 also computes Q.bk ----
    if (tid < ND) {
        float rr = 0.f;
        #pragma unroll 16
        for (int d = 0; d < ND; d++) rr += sQ[d] * __ldg(Wk + d * ND + tid);
        sR[tid] = rr;
    }
    if (tid >= 64 && tid < 96) {
        int t = tid - 64;
        float p = sQ[t] * __ldg(bk + t) + sQ[t + 32] * __ldg(bk + t + 32);
        #pragma unroll
        for (int off = 16; off; off >>= 1)
            p += __shfl_xor_sync(0xffffffffu, p, off);
        if (t == 0) sQbkSum = p;
    }
    __syncthreads();

    // ---- logit[u] = FACTOR * (r . sim_u + Q.bk) — all teams, no divergent shfl ----
    {
        int uu = (team < L) ? team : 0;
        float part = 0.f;
        #pragma unroll
        for (int j = 0; j < 4; j++) {
            int e = lane * 4 + j;
            part += sR[e] * sSim[uu][e];
        }
        #pragma unroll
        for (int off = 8; off; off >>= 1)
            part += __shfl_xor_sync(0xffffffffu, part, off, 16);
        if (lane == 0) sLogit[team] = FACTOR * (part + sQbkSum);
    }
    __syncthreads();

    // ---- masked softmax over the L users (warp 0) ----
    if (tid < 32) {
        int u = tid & 15;
        float v = (u < L) ? sLogit[u] : -3.402823466e38f;
        float m = v;
        #pragma unroll
        for (int off = 8; off; off >>= 1)
            m = fmaxf(m, __shfl_xor_sync(0xffffffffu, m, off, 16));
        float e = (u < L) ? __expf(v - m) : 0.f;
        float s = e;
        #pragma unroll
        for (int off = 8; off; off >>= 1)
            s += __shfl_xor_sync(0xffffffffu, s, off, 16);
        if (tid < 16) sWt[u] = e / s;
    }
    __syncthreads();

    // ---- build COMPACTED (id, w*count) list: warp-aggregated push ----
    {
        const int total = L * NB;
        const size_t base = (size_t)g * NU * NB;
        const int nIter = (total + 255) >> 8;
        for (int it = 0; it < nIter; it++) {
            int i = it * 256 + tid;
            bool valid = i < total;
            int id = 0; float c = 0.f;
            if (valid) {
                id = __ldg(beh_ids + base + i);
                c  = sWt[i / NB] * __ldg(beh_counts + base + i);
            }
            bool pred = valid && (c != 0.f);
            unsigned mask = __ballot_sync(0xffffffffu, pred);
            if (mask) {
                int ldr  = __ffs(mask) - 1;
                int rank = __popc(mask & ((1u << l32) - 1));
                int wbase = 0;
                if (l32 == ldr) wbase = atomicAdd(&sCnt, __popc(mask));
                wbase = __shfl_sync(0xffffffffu, wbase, ldr);
                if (pred) { sIds[wbase + rank] = id; sCoef[wbase + rank] = c; }
            }
        }
    }
    __syncthreads();
    const int n = sCnt;

    // ---- branch-free, balanced, high-MLP weighted gather-sum ----
    float4 acc = make_float4(0.f, 0.f, 0.f, 0.f);
    if (team < L) {   // seed with w[u] * user_table row
        float wgt = sWt[team];
        const float4* ur = (const float4*)(user_table + (size_t)sGid[team] * ND);
        float4 v = __ldg(ur + lane);
        acc.x = wgt * v.x; acc.y = wgt * v.y; acc.z = wgt * v.z; acc.w = wgt * v.w;
    }
    {
        int i = team;
        #pragma unroll 2
        for (; i + 48 < n; i += 64) {
            int   id0 = sIds[i],      id1 = sIds[i + 16],
                  id2 = sIds[i + 32], id3 = sIds[i + 48];
            float c0 = sCoef[i],      c1 = sCoef[i + 16],
                  c2 = sCoef[i + 32], c3 = sCoef[i + 48];
            float4 v0 = __ldg((const float4*)(item_table + (size_t)id0 * ND) + lane);
            float4 v1 = __ldg((const float4*)(item_table + (size_t)id1 * ND) + lane);
            float4 v2 = __ldg((const float4*)(item_table + (size_t)id2 * ND) + lane);
            float4 v3 = __ldg((const float4*)(item_table + (size_t)id3 * ND) + lane);
            acc.x += c0 * v0.x + c1 * v1.x + c2 * v2.x + c3 * v3.x;
            acc.y += c0 * v0.y + c1 * v1.y + c2 * v2.y + c3 * v3.y;
            acc.z += c0 * v0.z + c1 * v1.z + c2 * v2.z + c3 * v3.z;
            acc.w += c0 * v0.w + c1 * v1.w + c2 * v2.w + c3 * v3.w;
        }
        for (; i < n; i += 16) {
            int   id = sIds[i];
            float c  = sCoef[i];
            float4 v = __ldg((const float4*)(item_table + (size_t)id * ND) + lane);
            acc.x += c * v.x; acc.y += c * v.y; acc.z += c * v.z; acc.w += c * v.w;
        }
    }
    ((float4*)&sPool[team][0])[lane] = acc;
    __syncthreads();

    // ---- reduce 16 team accumulators ----
    if (tid < ND) {
        float s = 0.f;
        #pragma unroll
        for (int t = 0; t < 16; t++) s += sPool[t][tid];
        sPooled[tid] = s;
    }
    __syncthreads();

    // ---- out = Wv @ pooled + bv : 4 threads per row, coalesced ----
    {
        int d = tid >> 2, q = tid & 3;
        float p = 0.f;
        const float* w = Wv + d * ND + q * 16;
        const float* s = sPooled + q * 16;
        #pragma unroll
        for (int e = 0; e < 16; e++) p += __ldg(w + e) * s[e];
        p += __shfl_xor_sync(0xffffffffu, p, 1);
        p += __shfl_xor_sync(0xffffffffu, p, 2);
        if (q == 0) out[(size_t)g * ND + d] = p + __ldg(bv + d);
    }
}

extern "C" void kernel_launch(void* const* d_in, const int* in_sizes, int n_in,
                              void* d_out, int out_size)
{
    const int*   group_users = (const int*)  d_in[0];
    const int*   user_lens   = (const int*)  d_in[1];
    const int*   beh_ids     = (const int*)  d_in[2];
    const float* beh_counts  = (const float*)d_in[3];
    const int*   target_user = (const int*)  d_in[4];
    const float* user_table  = (const float*)d_in[5];
    const float* item_table  = (const float*)d_in[6];
    const float* sim_vec     = (const float*)d_in[7];
    const float* Wq          = (const float*)d_in[8];
    const float* bq          = (const float*)d_in[9];
    const float* Wk          = (const float*)d_in[10];
    const float* bk          = (const float*)d_in[11];
    const float* Wv          = (const float*)d_in[12];
    const float* bv          = (const float*)d_in[13];
    float*       out         = (float*)d_out;

    group_embedding_kernel<<<NG, 256>>>(
        group_users, user_lens, beh_ids, beh_counts, target_user,
        user_table, item_table, sim_vec,
        Wq, bq, Wk, bk, Wv, bv, out);
}

// round 5
// speedup vs baseline: 1.0349x; 1.0349x over previous
#include <cuda_runtime.h>

#define NG 2048
#define NU 16
#define NB 50
#define ND 64
#define FACTOR 0.5f

__global__ __launch_bounds__(256, 8)
void group_embedding_kernel(
    const int*   __restrict__ group_users,   // [G,U]
    const int*   __restrict__ user_lens,     // [G]
    const int*   __restrict__ beh_ids,       // [G,U,B]
    const float* __restrict__ beh_counts,    // [G,U,B]
    const int*   __restrict__ target_user,   // [G]
    const float* __restrict__ user_table,    // [N_USERS, D]
    const float* __restrict__ item_table,    // [N_ITEMS, D]
    const float* __restrict__ sim_vec,       // [N_USERS, D]
    const float* __restrict__ Wq, const float* __restrict__ bq,
    const float* __restrict__ Wk, const float* __restrict__ bk,
    const float* __restrict__ Wv, const float* __restrict__ bv,
    float*       __restrict__ out)           // [G, D]
{
    __shared__ float sTsim[ND];        // target similarity vector
    __shared__ float sQ[ND];
    __shared__ float sR[ND];           // r = Wk^T Q
    __shared__ float sLogit[NU];
    __shared__ float sWt[NU];
    __shared__ int   sGid[NU];
    __shared__ int   sIds[NU * NB];
    __shared__ float sCoef[NU * NB];
    __shared__ float sPool[16][ND];
    __shared__ float sPooled[ND];
    __shared__ float sQbkSum;

    const int g    = blockIdx.x;
    const int tid  = threadIdx.x;
    const int team = tid >> 4;      // 0..15
    const int lane = tid & 15;      // 0..15

    int L = user_lens[g];
    if (L < 1)  L = 1;
    if (L > NU) L = NU;

    // ---- Stage target sim vector + group ids ----
    if (tid < ND) sTsim[tid] = __ldg(sim_vec + (size_t)target_user[g] * ND + tid);
    if (tid >= 64 && tid < 64 + NU) sGid[tid - 64] = group_users[g * NU + (tid - 64)];
    __syncthreads();

    // ---- Q = Wq @ Tsim + bq : 4 threads per row, coalesced 2KB/warp ----
    {
        int d = tid >> 2, q = tid & 3;
        float p = 0.f;
        const float* w = Wq + d * ND + q * 16;
        const float* s = sTsim + q * 16;
        #pragma unroll
        for (int e = 0; e < 16; e++) p += __ldg(w + e) * s[e];
        p += __shfl_xor_sync(0xffffffffu, p, 1);
        p += __shfl_xor_sync(0xffffffffu, p, 2);
        if (q == 0) sQ[d] = p + __ldg(bq + d);
    }
    __syncthreads();

    // ---- r = Wk^T Q (coalesced columns); warp 2 computes Q.bk ----
    if (tid < ND) {
        float rr = 0.f;
        #pragma unroll 16
        for (int d = 0; d < ND; d++) rr += sQ[d] * __ldg(Wk + d * ND + tid);
        sR[tid] = rr;
    }
    if (tid >= 64 && tid < 96) {
        int t = tid - 64;
        float p = sQ[t] * __ldg(bk + t) + sQ[t + 32] * __ldg(bk + t + 32);
        #pragma unroll
        for (int off = 16; off; off >>= 1)
            p += __shfl_xor_sync(0xffffffffu, p, off);
        if (t == 0) sQbkSum = p;
    }
    __syncthreads();

    // ---- logit[u] = FACTOR * (r . sim_u + Q.bk): team u reads sim row direct ----
    {
        int uu = (team < L) ? team : 0;   // clamp; invalid teams' value discarded
        const float4* srow = (const float4*)(sim_vec + (size_t)sGid[uu] * ND);
        float4 sv = __ldg(srow + lane);
        const float* r4 = sR + lane * 4;
        float part = r4[0] * sv.x + r4[1] * sv.y + r4[2] * sv.z + r4[3] * sv.w;
        #pragma unroll
        for (int off = 8; off; off >>= 1)
            part += __shfl_xor_sync(0xffffffffu, part, off, 16);
        if (lane == 0) sLogit[team] = FACTOR * (part + sQbkSum);
    }
    __syncthreads();

    // ---- masked softmax over the L users (warp 0) ----
    if (tid < 32) {
        int u = tid & 15;
        float v = (u < L) ? sLogit[u] : -3.402823466e38f;
        float m = v;
        #pragma unroll
        for (int off = 8; off; off >>= 1)
            m = fmaxf(m, __shfl_xor_sync(0xffffffffu, m, off, 16));
        float e = (u < L) ? __expf(v - m) : 0.f;
        float s = e;
        #pragma unroll
        for (int off = 8; off; off >>= 1)
            s += __shfl_xor_sync(0xffffffffu, s, off, 16);
        if (tid < 16) sWt[u] = e / s;
    }
    __syncthreads();

    // ---- flat (id, w*count) item list for the L valid users ----
    const int total = L * NB;
    const size_t base = (size_t)g * NU * NB;
    for (int i = tid; i < total; i += 256) {
        int u = i / NB;
        sIds[i]  = __ldg(beh_ids + base + i);
        sCoef[i] = sWt[u] * __ldg(beh_counts + base + i);
    }
    __syncthreads();

    // ---- load-balanced weighted gather-sum (team-strided, branch skips zeros) ----
    float4 acc = make_float4(0.f, 0.f, 0.f, 0.f);
    if (team < L) {
        float wgt = sWt[team];
        const float4* ur = (const float4*)(user_table + (size_t)sGid[team] * ND);
        float4 v = __ldg(ur + lane);
        acc.x = wgt * v.x; acc.y = wgt * v.y; acc.z = wgt * v.z; acc.w = wgt * v.w;
    }
    #pragma unroll 4
    for (int i = team; i < total; i += 16) {
        float c = sCoef[i];
        if (c != 0.f) {
            const float4* row = (const float4*)(item_table + (size_t)sIds[i] * ND);
            float4 v = __ldg(row + lane);
            acc.x += c * v.x; acc.y += c * v.y; acc.z += c * v.z; acc.w += c * v.w;
        }
    }
    ((float4*)&sPool[team][0])[lane] = acc;
    __syncthreads();

    // ---- reduce the 16 team accumulators ----
    if (tid < ND) {
        float s = 0.f;
        #pragma unroll
        for (int t = 0; t < 16; t++) s += sPool[t][tid];
        sPooled[tid] = s;
    }
    __syncthreads();

    // ---- out = Wv @ pooled + bv : 4 threads per row, coalesced ----
    {
        int d = tid >> 2, q = tid & 3;
        float p = 0.f;
        const float* w = Wv + d * ND + q * 16;
        const float* s = sPooled + q * 16;
        #pragma unroll
        for (int e = 0; e < 16; e++) p += __ldg(w + e) * s[e];
        p += __shfl_xor_sync(0xffffffffu, p, 1);
        p += __shfl_xor_sync(0xffffffffu, p, 2);
        if (q == 0) out[(size_t)g * ND + d] = p + __ldg(bv + d);
    }
}

extern "C" void kernel_launch(void* const* d_in, const int* in_sizes, int n_in,
                              void* d_out, int out_size)
{
    const int*   group_users = (const int*)  d_in[0];
    const int*   user_lens   = (const int*)  d_in[1];
    const int*   beh_ids     = (const int*)  d_in[2];
    const float* beh_counts  = (const float*)d_in[3];
    const int*   target_user = (const int*)  d_in[4];
    const float* user_table  = (const float*)d_in[5];
    const float* item_table  = (const float*)d_in[6];
    const float* sim_vec     = (const float*)d_in[7];
    const float* Wq          = (const float*)d_in[8];
    const float* bq          = (const float*)d_in[9];
    const float* Wk          = (const float*)d_in[10];
    const float* bk          = (const float*)d_in[11];
    const float* Wv          = (const float*)d_in[12];
    const float* bv          = (const float*)d_in[13];
    float*       out         = (float*)d_out;

    group_embedding_kernel<<<NG, 256>>>(
        group_users, user_lens, beh_ids, beh_counts, target_user,
        user_table, item_table, sim_vec,
        Wq, bq, Wk, bk, Wv, bv, out);
}